// round 14
// baseline (speedup 1.0000x reference)
#include <cuda_runtime.h>
#include <cstdint>

// SparseTransE on GB300 — R14: entity rows via cp.async.bulk (UBLKCP) -> smem.
//
// R3/R13 plateau at ~40 µs / 71% DRAM-active with per-lane LDG gathers.
// Hypothesis: the LDG wavefront path caps in-flight DRAM bytes per SM.
// Replace the 2 entity-row gathers (h, t: 1 KB contiguous each) with
// single-instruction bulk async copies into shared memory, completed via an
// mbarrier per warp. Relation rows remain LDG (L2-resident). Compute is
// R3's measured-best two-phase reduction.
//
// Inputs (metadata order):
//   d_in[0] all_emb  : float32 [501000, 256]
//   d_in[1..3] pos_h/r/t : int32 [65536]
//   d_in[4..6] neg_h/r/t : int32 [65536]
// Output: float32 [131072] = concat(pos_scores, neg_scores)

#define N_BATCH 65536
#define EMB     256
#define N_ENT   500000
#define EPS2    1e-24f   // (1e-12)^2 — guard matches max(norm, 1e-12)
#define WARPS_PER_BLOCK 8

__device__ __forceinline__ uint32_t smem_u32(const void* p) {
    uint32_t a;
    asm("{ .reg .u64 t; cvta.to.shared.u64 t, %1; cvt.u32.u64 %0, t; }"
        : "=r"(a) : "l"(p));
    return a;
}

__device__ __forceinline__ void mbar_init(uint32_t mbar, uint32_t count) {
    asm volatile("mbarrier.init.shared.b64 [%0], %1;" :: "r"(mbar), "r"(count) : "memory");
}

__device__ __forceinline__ void mbar_expect_tx(uint32_t mbar, uint32_t bytes) {
    asm volatile("mbarrier.arrive.expect_tx.shared.b64 _, [%0], %1;"
                 :: "r"(mbar), "r"(bytes) : "memory");
}

__device__ __forceinline__ void bulk_copy_g2s(uint32_t dst_smem, const void* src,
                                              uint32_t bytes, uint32_t mbar) {
    asm volatile(
        "cp.async.bulk.shared::cluster.global.mbarrier::complete_tx::bytes "
        "[%0], [%1], %2, [%3];"
        :: "r"(dst_smem), "l"(src), "r"(bytes), "r"(mbar) : "memory");
}

__device__ __forceinline__ void mbar_wait(uint32_t mbar, uint32_t parity) {
    asm volatile(
        "{\n\t"
        ".reg .pred P;\n\t"
        "WAIT_%=:\n\t"
        "mbarrier.try_wait.parity.acquire.cta.shared::cta.b64 P, [%0], %1, 0x989680;\n\t"
        "@P bra.uni DONE_%=;\n\t"
        "bra.uni WAIT_%=;\n\t"
        "DONE_%=:\n\t"
        "}"
        :: "r"(mbar), "r"(parity) : "memory");
}

__global__ __launch_bounds__(32 * WARPS_PER_BLOCK)
void sparse_transe_kernel(
    const float* __restrict__ emb,
    const int*   __restrict__ pos_h,
    const int*   __restrict__ pos_r,
    const int*   __restrict__ pos_t,
    const int*   __restrict__ neg_h,
    const int*   __restrict__ neg_r,
    const int*   __restrict__ neg_t,
    float*       __restrict__ out)
{
    // Per-warp staging: h row + t row (1 KB each), 16-B+ aligned.
    __shared__ __align__(1024) float rows[WARPS_PER_BLOCK][2][EMB];
    __shared__ __align__(8)    unsigned long long mbar_storage[WARPS_PER_BLOCK];

    const int wlocal = threadIdx.x >> 5;
    const int lane   = threadIdx.x & 31;
    const int gwarp  = blockIdx.x * WARPS_PER_BLOCK + wlocal;  // 0..131071

    const int* __restrict__ H;
    const int* __restrict__ R;
    const int* __restrict__ T;
    int i;
    if (gwarp < N_BATCH) { H = pos_h; R = pos_r; T = pos_t; i = gwarp; }
    else                 { H = neg_h; R = neg_r; T = neg_t; i = gwarp - N_BATCH; }

    const long hrow = (long)__ldg(H + i) * EMB;
    const long trow = (long)__ldg(T + i) * EMB;
    const long rrow = ((long)__ldg(R + i) + N_ENT) * EMB;

    const uint32_t mbar   = smem_u32(&mbar_storage[wlocal]);
    const uint32_t smem_h = smem_u32(&rows[wlocal][0][0]);
    const uint32_t smem_t = smem_u32(&rows[wlocal][1][0]);

    // Lane 0: init barrier, fence it into the async proxy, kick both bulk
    // copies (2 KB expected).
    if (lane == 0) {
        mbar_init(mbar, 1);
        asm volatile("fence.proxy.async.shared::cta;" ::: "memory");
        mbar_expect_tx(mbar, 2 * EMB * (uint32_t)sizeof(float));
        bulk_copy_g2s(smem_h, emb + hrow, EMB * sizeof(float), mbar);
        bulk_copy_g2s(smem_t, emb + trow, EMB * sizeof(float), mbar);
    }

    // Relation row via LDG while the bulk copies are in flight (L2-resident).
    const float4* __restrict__ rp = (const float4*)(emb + rrow);
    float4 r0 = __ldg(rp + lane);
    float4 r1 = __ldg(rp + lane + 32);

    // Wait for the entity rows.
    mbar_wait(mbar, 0);

    const float4* hp = (const float4*)&rows[wlocal][0][0];
    const float4* tp = (const float4*)&rows[wlocal][1][0];
    float4 h0 = hp[lane];
    float4 h1 = hp[lane + 32];
    float4 t0 = tp[lane];
    float4 t1 = tp[lane + 32];

    // Partial squared norms of h and t.
    float sh = h0.x*h0.x + h0.y*h0.y + h0.z*h0.z + h0.w*h0.w
             + h1.x*h1.x + h1.y*h1.y + h1.z*h1.z + h1.w*h1.w;
    float st = t0.x*t0.x + t0.y*t0.y + t0.z*t0.z + t0.w*t0.w
             + t1.x*t1.x + t1.y*t1.y + t1.z*t1.z + t1.w*t1.w;

    #pragma unroll
    for (int off = 16; off > 0; off >>= 1) {
        sh += __shfl_xor_sync(0xffffffffu, sh, off);
        st += __shfl_xor_sync(0xffffffffu, st, off);
    }

    const float inv_h = rsqrtf(fmaxf(sh, EPS2));
    const float inv_t = rsqrtf(fmaxf(st, EPS2));

    float acc = 0.f;
    {
        float d;
        d = fmaf(h0.x, inv_h, r0.x) - t0.x * inv_t; acc = fmaf(d, d, acc);
        d = fmaf(h0.y, inv_h, r0.y) - t0.y * inv_t; acc = fmaf(d, d, acc);
        d = fmaf(h0.z, inv_h, r0.z) - t0.z * inv_t; acc = fmaf(d, d, acc);
        d = fmaf(h0.w, inv_h, r0.w) - t0.w * inv_t; acc = fmaf(d, d, acc);
        d = fmaf(h1.x, inv_h, r1.x) - t1.x * inv_t; acc = fmaf(d, d, acc);
        d = fmaf(h1.y, inv_h, r1.y) - t1.y * inv_t; acc = fmaf(d, d, acc);
        d = fmaf(h1.z, inv_h, r1.z) - t1.z * inv_t; acc = fmaf(d, d, acc);
        d = fmaf(h1.w, inv_h, r1.w) - t1.w * inv_t; acc = fmaf(d, d, acc);
    }

    #pragma unroll
    for (int off = 16; off > 0; off >>= 1)
        acc += __shfl_xor_sync(0xffffffffu, acc, off);

    if (lane == 0)
        out[gwarp] = -acc;
}

extern "C" void kernel_launch(void* const* d_in, const int* in_sizes, int n_in,
                              void* d_out, int out_size)
{
    const float* emb   = (const float*)d_in[0];
    const int*   pos_h = (const int*)d_in[1];
    const int*   pos_r = (const int*)d_in[2];
    const int*   pos_t = (const int*)d_in[3];
    const int*   neg_h = (const int*)d_in[4];
    const int*   neg_r = (const int*)d_in[5];
    const int*   neg_t = (const int*)d_in[6];
    float* out = (float*)d_out;

    // 131072 warps, 8 warps per block -> 16384 blocks.
    const int blocks = (2 * N_BATCH) / WARPS_PER_BLOCK;
    sparse_transe_kernel<<<blocks, 32 * WARPS_PER_BLOCK>>>(
        emb, pos_h, pos_r, pos_t, neg_h, neg_r, neg_t, out);
}

// round 17
// speedup vs baseline: 1.0671x; 1.0671x over previous
#include <cuda_runtime.h>
#include <cstdint>

// SparseTransE on GB300 — R17 (resubmit of R16; round 16 was an infra
// failure, the kernel never executed).
// R3 structure (best measured: 40.0 µs) with the six 128-bit row loads
// replaced by three 256-bit ld.global.nc.L2::evict_last.v8.b32 loads
// (ptxas on sm_103a permits evict_last only on v8.b32/v4.b64 — learned in
// R15). Lane i now covers floats [8i, 8i+8) of each row (32B aligned).
// Two stacked effects: evict_last retains gathered rows in L2 for
// duplicate-index hits (238 MB measured vs 207 MB unique floor), and LDG
// count per lane drops 6 -> 3, halving L1tex wavefront-queue pressure.
//
// Inputs (metadata order):
//   d_in[0] all_emb  : float32 [501000, 256]
//   d_in[1..3] pos_h/r/t : int32 [65536]
//   d_in[4..6] neg_h/r/t : int32 [65536]
// Output: float32 [131072] = concat(pos_scores, neg_scores)
//
// score(h,r,t) = -|| e[h]/max(||e[h]||,eps) + e[r+n_ent] - e[t]/max(||e[t]||,eps) ||^2

#define N_BATCH 65536
#define EMB     256
#define N_ENT   500000
#define EPS2    1e-24f   // (1e-12)^2 — guard matches max(norm, 1e-12)

struct F8 { float4 a, b; };

// 256-bit read-only load with L2 evict-last priority. p must be 32B aligned.
__device__ __forceinline__ F8 ldg_el_v8(const float* p) {
    uint32_t r0, r1, r2, r3, r4, r5, r6, r7;
    asm("ld.global.nc.L2::evict_last.v8.b32 {%0,%1,%2,%3,%4,%5,%6,%7}, [%8];"
        : "=r"(r0), "=r"(r1), "=r"(r2), "=r"(r3),
          "=r"(r4), "=r"(r5), "=r"(r6), "=r"(r7)
        : "l"(p));
    F8 v;
    v.a.x = __uint_as_float(r0); v.a.y = __uint_as_float(r1);
    v.a.z = __uint_as_float(r2); v.a.w = __uint_as_float(r3);
    v.b.x = __uint_as_float(r4); v.b.y = __uint_as_float(r5);
    v.b.z = __uint_as_float(r6); v.b.w = __uint_as_float(r7);
    return v;
}

__global__ __launch_bounds__(256)
void sparse_transe_kernel(
    const float* __restrict__ emb,
    const int*   __restrict__ pos_h,
    const int*   __restrict__ pos_r,
    const int*   __restrict__ pos_t,
    const int*   __restrict__ neg_h,
    const int*   __restrict__ neg_r,
    const int*   __restrict__ neg_t,
    float*       __restrict__ out)
{
    const int gwarp = (blockIdx.x * blockDim.x + threadIdx.x) >> 5;  // 0..131071
    const int lane  = threadIdx.x & 31;

    const int* __restrict__ H;
    const int* __restrict__ R;
    const int* __restrict__ T;
    int i;
    if (gwarp < N_BATCH) { H = pos_h; R = pos_r; T = pos_t; i = gwarp; }
    else                 { H = neg_h; R = neg_r; T = neg_t; i = gwarp - N_BATCH; }

    // Warp-uniform index loads — broadcast.
    const long hrow = (long)__ldg(H + i) * EMB;
    const long trow = (long)__ldg(T + i) * EMB;
    const long rrow = ((long)__ldg(R + i) + N_ENT) * EMB;

    // Lane i covers floats [8i, 8i+8) of each 256-float row.
    const int off = lane << 3;

    // Front-batch all 3 loads (entity rows first — DRAM latency; relation
    // row is L2-resident).
    F8 h = ldg_el_v8(emb + hrow + off);
    F8 t = ldg_el_v8(emb + trow + off);
    F8 r = ldg_el_v8(emb + rrow + off);

    // Partial squared norms of h and t.
    float sh = h.a.x*h.a.x + h.a.y*h.a.y + h.a.z*h.a.z + h.a.w*h.a.w
             + h.b.x*h.b.x + h.b.y*h.b.y + h.b.z*h.b.z + h.b.w*h.b.w;
    float st = t.a.x*t.a.x + t.a.y*t.a.y + t.a.z*t.a.z + t.a.w*t.a.w
             + t.b.x*t.b.x + t.b.y*t.b.y + t.b.z*t.b.z + t.b.w*t.b.w;

    // Fused butterfly reduction of (sh, st).
    #pragma unroll
    for (int o = 16; o > 0; o >>= 1) {
        sh += __shfl_xor_sync(0xffffffffu, sh, o);
        st += __shfl_xor_sync(0xffffffffu, st, o);
    }

    const float inv_h = rsqrtf(fmaxf(sh, EPS2));
    const float inv_t = rsqrtf(fmaxf(st, EPS2));

    // v = h/|h| + r - t/|t| ; accumulate v^2
    float acc = 0.f;
    {
        float d;
        d = fmaf(h.a.x, inv_h, r.a.x) - t.a.x * inv_t; acc = fmaf(d, d, acc);
        d = fmaf(h.a.y, inv_h, r.a.y) - t.a.y * inv_t; acc = fmaf(d, d, acc);
        d = fmaf(h.a.z, inv_h, r.a.z) - t.a.z * inv_t; acc = fmaf(d, d, acc);
        d = fmaf(h.a.w, inv_h, r.a.w) - t.a.w * inv_t; acc = fmaf(d, d, acc);
        d = fmaf(h.b.x, inv_h, r.b.x) - t.b.x * inv_t; acc = fmaf(d, d, acc);
        d = fmaf(h.b.y, inv_h, r.b.y) - t.b.y * inv_t; acc = fmaf(d, d, acc);
        d = fmaf(h.b.z, inv_h, r.b.z) - t.b.z * inv_t; acc = fmaf(d, d, acc);
        d = fmaf(h.b.w, inv_h, r.b.w) - t.b.w * inv_t; acc = fmaf(d, d, acc);
    }

    #pragma unroll
    for (int o = 16; o > 0; o >>= 1)
        acc += __shfl_xor_sync(0xffffffffu, acc, o);

    if (lane == 0)
        out[gwarp] = -acc;
}

extern "C" void kernel_launch(void* const* d_in, const int* in_sizes, int n_in,
                              void* d_out, int out_size)
{
    const float* emb   = (const float*)d_in[0];
    const int*   pos_h = (const int*)d_in[1];
    const int*   pos_r = (const int*)d_in[2];
    const int*   pos_t = (const int*)d_in[3];
    const int*   neg_h = (const int*)d_in[4];
    const int*   neg_r = (const int*)d_in[5];
    const int*   neg_t = (const int*)d_in[6];
    float* out = (float*)d_out;

    // 131072 warps, 8 warps (256 threads) per block -> 16384 blocks.
    const int blocks = (2 * N_BATCH) / 8;
    sparse_transe_kernel<<<blocks, 256>>>(
        emb, pos_h, pos_r, pos_t, neg_h, neg_r, neg_t, out);
}